// round 5
// baseline (speedup 1.0000x reference)
#include <cuda_runtime.h>
#include <math.h>

#define BB   256      // batch
#define SSZ  128      // seq len
#define HHD  512      // hidden
#define G4H  2048     // 4*H
#define KIN  414      // F*N
#define KINP 416      // padded K for float4
#define MTOT (SSZ*BB) // 32768

typedef unsigned long long u64;

// ---------------- packed f32x2 helpers (sm_103a FFMA2) ----------------------
__device__ __forceinline__ u64 pk2(float lo, float hi) {
    u64 r; asm("mov.b64 %0, {%1, %2};" : "=l"(r) : "f"(lo), "f"(hi)); return r;
}
__device__ __forceinline__ float2 upk2(u64 v) {
    float lo, hi; asm("mov.b64 {%0, %1}, %2;" : "=f"(lo), "=f"(hi) : "l"(v));
    return make_float2(lo, hi);
}
__device__ __forceinline__ u64 ffma2(u64 a, u64 b, u64 c) {
    u64 d; asm("fma.rn.f32x2 %0, %1, %2, %3;" : "=l"(d) : "l"(a), "l"(b), "l"(c));
    return d;
}
// 128-bit shared load returning two 64-bit packed operands
__device__ __forceinline__ void lds_v2(u64& x, u64& y, unsigned addr) {
    asm volatile("ld.shared.v2.b64 {%0, %1}, [%2];" : "=l"(x), "=l"(y) : "r"(addr));
}

// ---------------- scratch (device globals; no allocations allowed) ----------
__device__ __align__(256) float g_xs[MTOT * KINP];   // [S*B, 416]
__device__ __align__(256) float g_gx[MTOT * G4H];    // [S*B, 2048]
__device__ __align__(256) float g_h1[MTOT * HHD];    // layer1 hidden seq
__device__ __align__(256) float g_h2[MTOT * HHD];    // layer2 hidden seq
__device__ unsigned int g_bar;                        // grid barrier counter

__global__ void reset_bar_kernel() { g_bar = 0u; }

// ---------------- pack: x[B,F,N,S] -> xs[S*B, 416] (k = f*207+n, pad zeros) --
__global__ void pack_x_kernel(const float* __restrict__ x) {
    __shared__ float tile[32][33];
    int b  = blockIdx.x;
    int k0 = blockIdx.y * 32;
    int s0 = blockIdx.z * 32;
    int tx = threadIdx.x, ty = threadIdx.y;  // 32 x 8
    const float* xb = x + (size_t)b * KIN * SSZ;
#pragma unroll
    for (int i = 0; i < 4; i++) {
        int k = k0 + ty + 8 * i;
        if (k < KIN) tile[ty + 8 * i][tx] = xb[k * SSZ + s0 + tx];
    }
    __syncthreads();
#pragma unroll
    for (int i = 0; i < 4; i++) {
        int s = s0 + ty + 8 * i;
        int k = k0 + tx;
        if (k < KINP) {
            float v = (k < KIN) ? tile[tx][ty + 8 * i] : 0.f;
            g_xs[(s * BB + b) * KINP + k] = v;
        }
    }
}

// ---------------- big GEMM: 128x128 tile, 256 thr, per-thread 8x8 -----------
// C[m, n0+j] = A[m,:].W[j,:] + bias1 + bias2. A k-padded; W rows Kw cols.
__global__ __launch_bounds__(256) void gemm_big_kernel(
    const float* __restrict__ A, int lda, int Kpad,
    const float* __restrict__ W, int ldw, int Kw,
    const float* __restrict__ bias1, const float* __restrict__ bias2,
    float* __restrict__ out)
{
    __shared__ __align__(16) u64   As2[2][16][128];   // (a,a) dup pairs
    __shared__ __align__(16) float Bs [2][16][132];
    const unsigned sa = (unsigned)__cvta_generic_to_shared(&As2[0][0][0]);
    const unsigned sb = (unsigned)__cvta_generic_to_shared(&Bs [0][0][0]);
    const int tid = threadIdx.x;
    const int n0 = blockIdx.x * 128;
    const int m0 = blockIdx.y * 128;
    const int tx = tid & 15, ty = tid >> 4;     // 8 cols / 8 rows per thread
    const int sr = tid & 127;                    // staging row
    const int sk = (tid >> 7) * 8;               // staging k-offset (0 or 8)
    const int nk = Kpad / 16;

    u64 acc[8][4];
#pragma unroll
    for (int i = 0; i < 8; i++)
#pragma unroll
        for (int p = 0; p < 4; p++) acc[i][p] = 0ull;

    const float* Arow = A + (size_t)(m0 + sr) * lda;
    const float* Wrow = W + (size_t)(n0 + sr) * ldw;

    // stage tile 0
    {
        float4 a0 = *(const float4*)(Arow + sk);
        float4 a1 = *(const float4*)(Arow + sk + 4);
        As2[0][sk + 0][sr] = pk2(a0.x, a0.x); As2[0][sk + 1][sr] = pk2(a0.y, a0.y);
        As2[0][sk + 2][sr] = pk2(a0.z, a0.z); As2[0][sk + 3][sr] = pk2(a0.w, a0.w);
        As2[0][sk + 4][sr] = pk2(a1.x, a1.x); As2[0][sk + 5][sr] = pk2(a1.y, a1.y);
        As2[0][sk + 6][sr] = pk2(a1.z, a1.z); As2[0][sk + 7][sr] = pk2(a1.w, a1.w);
#pragma unroll
        for (int q = 0; q < 8; q++) {
            int k = sk + q;
            Bs[0][sk + q][sr] = (k < Kw) ? Wrow[k] : 0.f;
        }
    }
    __syncthreads();
    int buf = 0;
    const unsigned abase = sa + ty * 8 * 8;     // + (buf*16+k)*128*8
    const unsigned bbase = sb + tx * 8 * 4;     // + (buf*16+k)*132*4
    for (int kt = 0; kt < nk; kt++) {
        float4 a0n, a1n; float bn[8];
        bool next = (kt + 1 < nk);
        if (next) {
            int kb = (kt + 1) * 16;
            a0n = *(const float4*)(Arow + kb + sk);
            a1n = *(const float4*)(Arow + kb + sk + 4);
#pragma unroll
            for (int q = 0; q < 8; q++) {
                int k = kb + sk + q;
                bn[q] = (k < Kw) ? Wrow[k] : 0.f;
            }
        }
        unsigned aoff = abase + (unsigned)buf * (16 * 128 * 8);
        unsigned boff = bbase + (unsigned)buf * (16 * 132 * 4);
#pragma unroll
        for (int k = 0; k < 16; k++) {
            u64 ad[8], b[4];
            lds_v2(ad[0], ad[1], aoff + k * (128 * 8));
            lds_v2(ad[2], ad[3], aoff + k * (128 * 8) + 16);
            lds_v2(ad[4], ad[5], aoff + k * (128 * 8) + 32);
            lds_v2(ad[6], ad[7], aoff + k * (128 * 8) + 48);
            lds_v2(b[0], b[1], boff + k * (132 * 4));
            lds_v2(b[2], b[3], boff + k * (132 * 4) + 16);
#pragma unroll
            for (int i = 0; i < 8; i++) {
                acc[i][0] = ffma2(ad[i], b[0], acc[i][0]);
                acc[i][1] = ffma2(ad[i], b[1], acc[i][1]);
                acc[i][2] = ffma2(ad[i], b[2], acc[i][2]);
                acc[i][3] = ffma2(ad[i], b[3], acc[i][3]);
            }
        }
        if (next) {
            int nb = buf ^ 1;
            As2[nb][sk + 0][sr] = pk2(a0n.x, a0n.x); As2[nb][sk + 1][sr] = pk2(a0n.y, a0n.y);
            As2[nb][sk + 2][sr] = pk2(a0n.z, a0n.z); As2[nb][sk + 3][sr] = pk2(a0n.w, a0n.w);
            As2[nb][sk + 4][sr] = pk2(a1n.x, a1n.x); As2[nb][sk + 5][sr] = pk2(a1n.y, a1n.y);
            As2[nb][sk + 6][sr] = pk2(a1n.z, a1n.z); As2[nb][sk + 7][sr] = pk2(a1n.w, a1n.w);
#pragma unroll
            for (int q = 0; q < 8; q++) Bs[nb][sk + q][sr] = bn[q];
            __syncthreads();
            buf = nb;
        }
    }
    // epilogue: 8 rows x 8 cols, bias add
    int j0 = n0 + tx * 8;
    float bsv[8];
#pragma unroll
    for (int q = 0; q < 8; q++) bsv[q] = bias1[j0 + q] + bias2[j0 + q];
#pragma unroll
    for (int i = 0; i < 8; i++) {
        int m = m0 + ty * 8 + i;
        float2 p0 = upk2(acc[i][0]), p1 = upk2(acc[i][1]);
        float2 p2 = upk2(acc[i][2]), p3 = upk2(acc[i][3]);
        float4 o0, o1;
        o0.x = p0.x + bsv[0]; o0.y = p0.y + bsv[1]; o0.z = p1.x + bsv[2]; o0.w = p1.y + bsv[3];
        o1.x = p2.x + bsv[4]; o1.y = p2.y + bsv[5]; o1.z = p3.x + bsv[6]; o1.w = p3.y + bsv[7];
        *(float4*)(out + (size_t)m * G4H + j0)     = o0;
        *(float4*)(out + (size_t)m * G4H + j0 + 4) = o1;
    }
}

// ---------------- persistent LSTM recurrence --------------------------------
// 128 CTAs = 4 batch-blocks(64) x 32 col-blocks(64 gate-cols = 16 hh x 4 gates).
// Resident W in smem (swizzled cols), per-thread 2(M)x8(N), c-state in regs.
#define WRS 68
#define WS_BYTES (512 * WRS * 4)
#define SMEM_PERSIST (WS_BYTES + 2 * 16 * 64 * 8)

__global__ __launch_bounds__(256, 1) void lstm_persist_kernel(
    const float* __restrict__ gx,   // [S*B, 2048] (biases folded in)
    const float* __restrict__ whh,  // [2048, 512]
    float* __restrict__ hseq)       // [S*B, 512]
{
    extern __shared__ float sm[];
    float* Ws  = sm;                          // [512][68] swizzled columns
    u64*   As2 = (u64*)(sm + 512 * WRS);      // [2][16][64] dup pairs
    const unsigned sbase = (unsigned)__cvta_generic_to_shared(sm);
    const unsigned sA = sbase + WS_BYTES;
    const int tid = threadIdx.x;
    const int bid = blockIdx.x;
    const int m0  = (bid & 3) * 64;
    const int hh0 = (bid >> 2) * 16;
    const int tn = tid & 7;        // n-group: 8 cols = 2 hh x 4 gates
    const int tm = tid >> 3;       // m-pair: batches 2tm, 2tm+1
    const int lm = tid >> 2, lk = (tid & 3) * 4;  // W staging
    const int sr = tid & 63, sk = (tid >> 6) * 4; // A staging

    // stage W: col c -> gate row j = (c&3)*512 + hh0 + (c>>2); swizzle word(c)=c+((c>>5)<<2)
    {
        int c  = lm;
        int wc = c + ((c >> 5) << 2);
        int j  = (c & 3) * HHD + hh0 + (c >> 2);
        const float* wr = whh + (size_t)j * HHD;
#pragma unroll 4
        for (int kt = 0; kt < 32; kt++) {
            float4 w4 = *(const float4*)(wr + kt * 16 + lk);
            Ws[(kt * 16 + lk + 0) * WRS + wc] = w4.x;
            Ws[(kt * 16 + lk + 1) * WRS + wc] = w4.y;
            Ws[(kt * 16 + lk + 2) * WRS + wc] = w4.z;
            Ws[(kt * 16 + lk + 3) * WRS + wc] = w4.w;
        }
    }
    __syncthreads();

    const int bw0 = 8 * tn + ((tn >= 4) ? 4 : 0);
    const unsigned bbase = sbase + bw0 * 4;     // + k*WRS*4
    const unsigned abase = sA + 2 * tm * 8;     // + (buf*16+k)*64*8

    float cc[4] = {0.f, 0.f, 0.f, 0.f};        // [mi*2+hhi]

    for (int t = 0; t < SSZ; t++) {
        // prefetch gx for this step: 2 batches x 2 hh x 4 gates
        float gxr[16];
        const float* gxt = gx + (size_t)t * BB * G4H;
#pragma unroll
        for (int mi = 0; mi < 2; mi++)
#pragma unroll
            for (int hhi = 0; hhi < 2; hhi++) {
                const float* p = gxt + (size_t)(m0 + 2 * tm + mi) * G4H + hh0 + 2 * tn + hhi;
#pragma unroll
                for (int g = 0; g < 4; g++)
                    gxr[mi * 8 + hhi * 4 + g] = __ldcg(p + g * HHD);
            }

        u64 acc[2][4];
#pragma unroll
        for (int i = 0; i < 2; i++)
#pragma unroll
            for (int p = 0; p < 4; p++) acc[i][p] = 0ull;

        if (t > 0) {
            const float* hp = hseq + (size_t)(t - 1) * BB * HHD;
            const float* hrow = hp + (size_t)(m0 + sr) * HHD;
            {
                float4 a4 = __ldcg((const float4*)(hrow + sk));
                As2[(sk + 0) * 64 + sr] = pk2(a4.x, a4.x);
                As2[(sk + 1) * 64 + sr] = pk2(a4.y, a4.y);
                As2[(sk + 2) * 64 + sr] = pk2(a4.z, a4.z);
                As2[(sk + 3) * 64 + sr] = pk2(a4.w, a4.w);
            }
            __syncthreads();
            int buf = 0;
            for (int kt = 0; kt < 32; kt++) {
                float4 a4n;
                bool nxt = (kt + 1 < 32);
                if (nxt) a4n = __ldcg((const float4*)(hrow + (kt + 1) * 16 + sk));
                unsigned aoff = abase + (unsigned)buf * (16 * 64 * 8);
                unsigned boff = bbase + (unsigned)(kt * 16) * (WRS * 4);
#pragma unroll
                for (int k = 0; k < 16; k++) {
                    u64 a0, a1, b01, b23, b45, b67;
                    lds_v2(a0, a1, aoff + k * (64 * 8));
                    lds_v2(b01, b23, boff + k * (WRS * 4));
                    lds_v2(b45, b67, boff + k * (WRS * 4) + 16);
                    acc[0][0] = ffma2(a0, b01, acc[0][0]);
                    acc[0][1] = ffma2(a0, b23, acc[0][1]);
                    acc[0][2] = ffma2(a0, b45, acc[0][2]);
                    acc[0][3] = ffma2(a0, b67, acc[0][3]);
                    acc[1][0] = ffma2(a1, b01, acc[1][0]);
                    acc[1][1] = ffma2(a1, b23, acc[1][1]);
                    acc[1][2] = ffma2(a1, b45, acc[1][2]);
                    acc[1][3] = ffma2(a1, b67, acc[1][3]);
                }
                if (nxt) {
                    int nb = buf ^ 1;
                    As2[(nb * 16 + sk + 0) * 64 + sr] = pk2(a4n.x, a4n.x);
                    As2[(nb * 16 + sk + 1) * 64 + sr] = pk2(a4n.y, a4n.y);
                    As2[(nb * 16 + sk + 2) * 64 + sr] = pk2(a4n.z, a4n.z);
                    As2[(nb * 16 + sk + 3) * 64 + sr] = pk2(a4n.w, a4n.w);
                    __syncthreads();
                    buf = nb;
                }
            }
        }

        // gates + state: acc[mi][2*hhi]=(i,f), acc[mi][2*hhi+1]=(g,o) for hh=hh0+2tn+hhi
        float* hout = hseq + (size_t)t * BB * HHD;
#pragma unroll
        for (int mi = 0; mi < 2; mi++) {
#pragma unroll
            for (int hhi = 0; hhi < 2; hhi++) {
                float2 pA = upk2(acc[mi][2 * hhi]);
                float2 pB = upk2(acc[mi][2 * hhi + 1]);
                float r0 = pA.x + gxr[mi * 8 + hhi * 4 + 0];
                float r1 = pA.y + gxr[mi * 8 + hhi * 4 + 1];
                float r2 = pB.x + gxr[mi * 8 + hhi * 4 + 2];
                float r3 = pB.y + gxr[mi * 8 + hhi * 4 + 3];
                float ig = 1.f / (1.f + __expf(-r0));
                float fg = 1.f / (1.f + __expf(-r1));
                float gg = tanhf(r2);
                float og = 1.f / (1.f + __expf(-r3));
                float cn = ig * gg + fg * cc[mi * 2 + hhi];
                cc[mi * 2 + hhi] = cn;
                hout[(size_t)(m0 + 2 * tm + mi) * HHD + hh0 + 2 * tn + hhi] = og * tanhf(cn);
            }
        }

        // grid barrier: release h_t before step t+1
        if (t + 1 < SSZ) {
            __syncthreads();
            if (tid == 0) {
                __threadfence();
                atomicAdd(&g_bar, 1u);
                unsigned tgt = (unsigned)(t + 1) * gridDim.x;
                unsigned v;
                do {
                    asm volatile("ld.global.acquire.gpu.u32 %0, [%1];" : "=r"(v) : "l"(&g_bar));
                } while (v < tgt);
            }
            __syncthreads();
        }
    }
}

// ---------------- FC head: 128x128 tile, transpose store --------------------
__global__ __launch_bounds__(256) void fc_kernel(
    const float* __restrict__ A,     // g_h2 [32768, 512]
    const float* __restrict__ W,     // fc_w [414, 512]
    const float* __restrict__ bias,  // fc_b [414]
    float* __restrict__ out)         // [256, 2, 207, 128]
{
    __shared__ __align__(16) u64   As2[2][16][128];
    __shared__ __align__(16) float Bs [2][16][132];
    const unsigned sa = (unsigned)__cvta_generic_to_shared(&As2[0][0][0]);
    const unsigned sb = (unsigned)__cvta_generic_to_shared(&Bs [0][0][0]);
    const int tid = threadIdx.x;
    const int n0 = blockIdx.x * 128;
    const int m0 = blockIdx.y * 128;
    const int tx = tid & 15, ty = tid >> 4;
    const int sr = tid & 127;
    const int sk = (tid >> 7) * 8;

    u64 acc[8][4];
#pragma unroll
    for (int i = 0; i < 8; i++)
#pragma unroll
        for (int p = 0; p < 4; p++) acc[i][p] = 0ull;

    const float* Arow = A + (size_t)(m0 + sr) * HHD;
    const bool jvrow = (n0 + sr) < KIN;
    const float* Wrow = W + (size_t)(jvrow ? (n0 + sr) : 0) * HHD;

    {
        float4 a0 = *(const float4*)(Arow + sk);
        float4 a1 = *(const float4*)(Arow + sk + 4);
        As2[0][sk + 0][sr] = pk2(a0.x, a0.x); As2[0][sk + 1][sr] = pk2(a0.y, a0.y);
        As2[0][sk + 2][sr] = pk2(a0.z, a0.z); As2[0][sk + 3][sr] = pk2(a0.w, a0.w);
        As2[0][sk + 4][sr] = pk2(a1.x, a1.x); As2[0][sk + 5][sr] = pk2(a1.y, a1.y);
        As2[0][sk + 6][sr] = pk2(a1.z, a1.z); As2[0][sk + 7][sr] = pk2(a1.w, a1.w);
        float4 w0 = jvrow ? *(const float4*)(Wrow + sk)     : make_float4(0, 0, 0, 0);
        float4 w1 = jvrow ? *(const float4*)(Wrow + sk + 4) : make_float4(0, 0, 0, 0);
        Bs[0][sk + 0][sr] = w0.x; Bs[0][sk + 1][sr] = w0.y;
        Bs[0][sk + 2][sr] = w0.z; Bs[0][sk + 3][sr] = w0.w;
        Bs[0][sk + 4][sr] = w1.x; Bs[0][sk + 5][sr] = w1.y;
        Bs[0][sk + 6][sr] = w1.z; Bs[0][sk + 7][sr] = w1.w;
    }
    __syncthreads();
    int buf = 0;
    const unsigned abase = sa + ty * 8 * 8;
    const unsigned bbase = sb + tx * 8 * 4;
    for (int kt = 0; kt < 32; kt++) {
        float4 a0n, a1n, w0n, w1n;
        bool next = (kt + 1 < 32);
        if (next) {
            int kb = (kt + 1) * 16;
            a0n = *(const float4*)(Arow + kb + sk);
            a1n = *(const float4*)(Arow + kb + sk + 4);
            w0n = jvrow ? *(const float4*)(Wrow + kb + sk)     : make_float4(0, 0, 0, 0);
            w1n = jvrow ? *(const float4*)(Wrow + kb + sk + 4) : make_float4(0, 0, 0, 0);
        }
        unsigned aoff = abase + (unsigned)buf * (16 * 128 * 8);
        unsigned boff = bbase + (unsigned)buf * (16 * 132 * 4);
#pragma unroll
        for (int k = 0; k < 16; k++) {
            u64 ad[8], b[4];
            lds_v2(ad[0], ad[1], aoff + k * (128 * 8));
            lds_v2(ad[2], ad[3], aoff + k * (128 * 8) + 16);
            lds_v2(ad[4], ad[5], aoff + k * (128 * 8) + 32);
            lds_v2(ad[6], ad[7], aoff + k * (128 * 8) + 48);
            lds_v2(b[0], b[1], boff + k * (132 * 4));
            lds_v2(b[2], b[3], boff + k * (132 * 4) + 16);
#pragma unroll
            for (int i = 0; i < 8; i++) {
                acc[i][0] = ffma2(ad[i], b[0], acc[i][0]);
                acc[i][1] = ffma2(ad[i], b[1], acc[i][1]);
                acc[i][2] = ffma2(ad[i], b[2], acc[i][2]);
                acc[i][3] = ffma2(ad[i], b[3], acc[i][3]);
            }
        }
        if (next) {
            int nb = buf ^ 1;
            As2[nb][sk + 0][sr] = pk2(a0n.x, a0n.x); As2[nb][sk + 1][sr] = pk2(a0n.y, a0n.y);
            As2[nb][sk + 2][sr] = pk2(a0n.z, a0n.z); As2[nb][sk + 3][sr] = pk2(a0n.w, a0n.w);
            As2[nb][sk + 4][sr] = pk2(a1n.x, a1n.x); As2[nb][sk + 5][sr] = pk2(a1n.y, a1n.y);
            As2[nb][sk + 6][sr] = pk2(a1n.z, a1n.z); As2[nb][sk + 7][sr] = pk2(a1n.w, a1n.w);
            Bs[nb][sk + 0][sr] = w0n.x; Bs[nb][sk + 1][sr] = w0n.y;
            Bs[nb][sk + 2][sr] = w0n.z; Bs[nb][sk + 3][sr] = w0n.w;
            Bs[nb][sk + 4][sr] = w1n.x; Bs[nb][sk + 5][sr] = w1n.y;
            Bs[nb][sk + 6][sr] = w1n.z; Bs[nb][sk + 7][sr] = w1n.w;
            __syncthreads();
            buf = nb;
        }
    }
    // epilogue: transpose store out[b, oc, n, s]; j guard < 414
    float accf[8][8];
#pragma unroll
    for (int i = 0; i < 8; i++) {
        float2 p0 = upk2(acc[i][0]), p1 = upk2(acc[i][1]);
        float2 p2 = upk2(acc[i][2]), p3 = upk2(acc[i][3]);
        accf[i][0] = p0.x; accf[i][1] = p0.y; accf[i][2] = p1.x; accf[i][3] = p1.y;
        accf[i][4] = p2.x; accf[i][5] = p2.y; accf[i][6] = p3.x; accf[i][7] = p3.y;
    }
#pragma unroll
    for (int i = 0; i < 8; i++) {
        int m = m0 + ty * 8 + i;
        int s = m >> 8;          // m = s*256 + b
        int b = m & 255;
#pragma unroll
        for (int jj = 0; jj < 8; jj++) {
            int j = n0 + tx * 8 + jj;
            if (j < KIN) {
                int oc = j / 207;
                int n  = j - oc * 207;
                out[(size_t)((b * 2 + oc) * 207 + n) * SSZ + s] = accf[i][jj] + bias[j];
            }
        }
    }
}

// ---------------- launch -----------------------------------------------------
extern "C" void kernel_launch(void* const* d_in, const int* in_sizes, int n_in,
                              void* d_out, int out_size)
{
    const float* x     = (const float*)d_in[0];
    const float* w_ih0 = (const float*)d_in[1];
    const float* w_hh0 = (const float*)d_in[2];
    const float* b_ih0 = (const float*)d_in[3];
    const float* b_hh0 = (const float*)d_in[4];
    const float* w_ih1 = (const float*)d_in[5];
    const float* w_hh1 = (const float*)d_in[6];
    const float* b_ih1 = (const float*)d_in[7];
    const float* b_hh1 = (const float*)d_in[8];
    const float* fc_w  = (const float*)d_in[9];
    const float* fc_b  = (const float*)d_in[10];
    float* out = (float*)d_out;

    float *xs, *gx, *h1, *h2;
    cudaGetSymbolAddress((void**)&xs, g_xs);
    cudaGetSymbolAddress((void**)&gx, g_gx);
    cudaGetSymbolAddress((void**)&h1, g_h1);
    cudaGetSymbolAddress((void**)&h2, g_h2);

    cudaFuncSetAttribute(lstm_persist_kernel,
                         cudaFuncAttributeMaxDynamicSharedMemorySize, SMEM_PERSIST);

    // 1) pack x -> xs [S*B, 416]
    pack_x_kernel<<<dim3(256, 13, 4), dim3(32, 8)>>>(x);

    // 2) gx = xs @ w_ih0^T + b_ih0 + b_hh0
    gemm_big_kernel<<<dim3(G4H / 128, MTOT / 128), 256>>>(
        xs, KINP, KINP, w_ih0, KIN, KIN, b_ih0, b_hh0, gx);

    // 3) layer 1 recurrence (persistent, grid-sync per step)
    reset_bar_kernel<<<1, 1>>>();
    lstm_persist_kernel<<<128, 256, SMEM_PERSIST>>>(gx, w_hh0, h1);

    // 4) gx = h1 @ w_ih1^T + b_ih1 + b_hh1
    gemm_big_kernel<<<dim3(G4H / 128, MTOT / 128), 256>>>(
        h1, HHD, HHD, w_ih1, HHD, HHD, b_ih1, b_hh1, gx);

    // 5) layer 2 recurrence
    reset_bar_kernel<<<1, 1>>>();
    lstm_persist_kernel<<<128, 256, SMEM_PERSIST>>>(gx, w_hh1, h2);

    // 6) FC head + output transpose
    fc_kernel<<<dim3(4, MTOT / 128), 256>>>(h2, fc_w, fc_b, out);
}